// round 14
// baseline (speedup 1.0000x reference)
#include <cuda_runtime.h>
#include <cstdint>

#define BB 64
#define NN 64
#define TT 16
#define DD 512
#define RR (BB*NN)          // 4096 rows (b,m)
#define THR2 (150.0f*150.0f)

// ---------------- scratch (device globals, no allocation) ----------------
__device__ float g_agg[RR*DD];      // aggregation output  [r][c]
__device__ float g_z[RR*DD];        // K-split partial 0, then final z
__device__ float g_z2[RR*DD];       // K-split partial 1
__device__ float g_psum[64*DD];     // BN partial sums   [rTile][col]
__device__ float g_psq[64*DD];      // BN partial sumsq  [rTile][col]
__device__ float g_scale[DD];
__device__ float g_shift[DD];

// ---------------- warmup (forces stream resource materialization pre-main) --
__global__ void k_warm() {}

// ---------------- side-stream copy: out[:, :, t!=15, :] = pf ----------------
// grid-stride, 296 blocks x 256 threads; flat index over the t<15 region:
// e = r*1920 + (tt*128 + w)  ->  gmem idx = r*2048 + (e - r*1920)
__global__ void __launch_bounds__(256) k_copy15(const float4* __restrict__ src,
                                                float4* __restrict__ dst) {
    const int total = RR * 15 * 128;       // 7,864,320 float4
    int stride = gridDim.x * 256;
    #pragma unroll 4
    for (int e = blockIdx.x * 256 + threadIdx.x; e < total; e += stride) {
        int r   = e / 1920;
        int rem = e - r * 1920;
        size_t idx = (size_t)r * 2048 + rem;
        dst[idx] = src[idx];
    }
}

// ---------------- common MMA helper ----------------
__device__ __forceinline__ void mma_tf32(float* c, const uint32_t* a, const uint32_t* b) {
    asm volatile(
        "mma.sync.aligned.m16n8k8.row.col.f32.tf32.tf32.f32 "
        "{%0,%1,%2,%3}, {%4,%5,%6,%7}, {%8,%9}, {%0,%1,%2,%3};"
        : "+f"(c[0]), "+f"(c[1]), "+f"(c[2]), "+f"(c[3])
        : "r"(a[0]), "r"(a[1]), "r"(a[2]), "r"(a[3]), "r"(b[0]), "r"(b[1]));
}
__device__ __forceinline__ void cp16(uint32_t dst, const void* src) {
    asm volatile("cp.async.ca.shared.global [%0], [%1], 16;" :: "r"(dst), "l"(src));
}
#define CP_COMMIT() asm volatile("cp.async.commit_group;" ::: "memory")
#define CP_WAIT0()  asm volatile("cp.async.wait_group 0;" ::: "memory")

// ---------------- graph aggregation via tf32 MMA (adjacency fused) ----------------
#define AGG_LD 68
__global__ void __launch_bounds__(128) k_agg(const float* __restrict__ pf,
                                             const float* __restrict__ bbx, int mode) {
    __shared__ float Asm[NN*AGG_LD];    // [m][n] stride 68
    __shared__ float Xs[NN*AGG_LD];     // [n][c] stride 68
    __shared__ float cx[NN], cy[NN], invdeg[NN];
    int b = blockIdx.x;
    int cBase = blockIdx.y * 64;
    int t = threadIdx.x;
    int lane = t & 31, wid = t >> 5;
    int wm = wid >> 1, wn = wid & 1;     // 2x2 warps: 32 rows x 32 cols each

    if (t < NN) {
        const float* p = bbx + (b*NN + t)*4;
        cx[t] = p[0] + 0.5f*p[2];
        cy[t] = p[1] + 0.5f*p[3];
    }
    __syncthreads();
    if (t < NN) {
        float x0 = cx[t], y0 = cy[t];
        int cnt = 0;
        #pragma unroll 8
        for (int m = 0; m < NN; m++) {
            float dx = x0 - cx[m], dy = y0 - cy[m];
            if (m != t && dx*dx + dy*dy < THR2) cnt++;
        }
        invdeg[t] = 1.0f / ((float)(cnt + 1) + 1e-6f);
    }
    __syncthreads();
    #pragma unroll
    for (int i = 0; i < 32; i++) {
        int e = t + 128*i;
        int m = e >> 6, n = e & 63;
        float dx = cx[n]-cx[m], dy = cy[n]-cy[m];
        float d2 = dx*dx + dy*dy;
        Asm[m*AGG_LD + n] = (n == m || d2 < THR2) ? invdeg[n] : 0.0f;
    }
    #pragma unroll
    for (int i = 0; i < 8; i++) {
        int e  = t + 128*i;          // 0..1023
        int n  = e >> 4;
        int cg = (e & 15) * 4;
        float4 v;
        if (mode == 0) {
            v = *(const float4*)&pf[((b*NN + n)*TT + 15)*DD + cBase + cg];
        } else {
            float4 z  = *(const float4*)&g_z[(b*NN + n)*DD + cBase + cg];
            float4 sc = *(const float4*)&g_scale[cBase + cg];
            float4 sh = *(const float4*)&g_shift[cBase + cg];
            v.x = fmaxf(fmaf(z.x, sc.x, sh.x), 0.0f);
            v.y = fmaxf(fmaf(z.y, sc.y, sh.y), 0.0f);
            v.z = fmaxf(fmaf(z.z, sc.z, sh.z), 0.0f);
            v.w = fmaxf(fmaf(z.w, sc.w, sh.w), 0.0f);
        }
        *(float4*)&Xs[n*AGG_LD + cg] = v;
    }
    __syncthreads();

    float acc[2][4][4];
    #pragma unroll
    for (int mt = 0; mt < 2; mt++)
        #pragma unroll
        for (int nt = 0; nt < 4; nt++)
            #pragma unroll
            for (int j = 0; j < 4; j++) acc[mt][nt][j] = 0.0f;

    int ar = wm*32 + (lane >> 2);
    int bc = wn*32 + (lane >> 2);
    #pragma unroll
    for (int ks = 0; ks < 8; ks++) {
        uint32_t af[2][4], bf[4][2];
        #pragma unroll
        for (int mt = 0; mt < 2; mt++)
            #pragma unroll
            for (int j = 0; j < 4; j++)
                af[mt][j] = __float_as_uint(
                    Asm[(ar + mt*16 + 8*(j&1))*AGG_LD + ks*8 + (lane&3) + 4*(j>>1)]);
        #pragma unroll
        for (int nt = 0; nt < 4; nt++)
            #pragma unroll
            for (int j = 0; j < 2; j++)
                bf[nt][j] = __float_as_uint(
                    Xs[(ks*8 + (lane&3) + 4*j)*AGG_LD + bc + nt*8]);
        #pragma unroll
        for (int mt = 0; mt < 2; mt++)
            #pragma unroll
            for (int nt = 0; nt < 4; nt++)
                mma_tf32(acc[mt][nt], af[mt], bf[nt]);
    }

    #pragma unroll
    for (int nt = 0; nt < 4; nt++) {
        int col = cBase + wn*32 + nt*8 + (lane & 3)*2;
        #pragma unroll
        for (int mt = 0; mt < 2; mt++) {
            int row0 = b*NN + wm*32 + mt*16 + (lane >> 2);
            *(float2*)&g_agg[row0*DD + col]     = make_float2(acc[mt][nt][0], acc[mt][nt][1]);
            *(float2*)&g_agg[(row0+8)*DD + col] = make_float2(acc[mt][nt][2], acc[mt][nt][3]);
        }
    }
}

// ---------------- tf32 mma.sync GEMM, split-K=2, partial output -------------
// partial[r][o] = sum_{c in K-half} g_agg[r][c]*W[o][c]
// Block 64x128 over K=256 (8 chunks), 8 warps (2M x 4N), warp tile 32x32.
#define LDK 36
#define ABUF(b) ((b)*2304)
#define BBUF(b) (4608 + (b)*4608)
#define GEMM_SMEM (13824*4)     // 54KB

__global__ void __launch_bounds__(256, 3) k_gemm_mma(const float* __restrict__ W) {
    extern __shared__ float sm[];
    uint32_t sbase = (uint32_t)__cvta_generic_to_shared(sm);
    int t = threadIdx.x;
    int lane = t & 31;
    int wid = t >> 5;
    int wm = wid >> 2, wn = wid & 3;
    int rBase = blockIdx.x * 64;
    int oBase = blockIdx.y * 128;
    int kBase = blockIdx.z * 256;
    float* Z = blockIdx.z ? g_z2 : g_z;
    const float* A = g_agg;

    int frow = t >> 3, fcg = (t & 7) * 4;
    int aBase = (wm*32 + (lane >> 2))*LDK + (lane & 3);
    int bBase = (wn*32 + (lane >> 2))*LDK + (lane & 3);

    float acc[2][4][4];
    #pragma unroll
    for (int mt = 0; mt < 2; mt++)
        #pragma unroll
        for (int nt = 0; nt < 4; nt++)
            #pragma unroll
            for (int j = 0; j < 4; j++) acc[mt][nt][j] = 0.0f;

    {
        #pragma unroll
        for (int i = 0; i < 2; i++) {
            int row = frow + 32*i;
            cp16(sbase + (ABUF(0) + row*LDK + fcg)*4, &A[(rBase+row)*DD + kBase + fcg]);
        }
        #pragma unroll
        for (int i = 0; i < 4; i++) {
            int row = frow + 32*i;
            cp16(sbase + (BBUF(0) + row*LDK + fcg)*4, &W[(oBase+row)*DD + kBase + fcg]);
        }
        CP_COMMIT();
        CP_WAIT0();
        __syncthreads();
    }

    #pragma unroll 1
    for (int it = 0; it < 8; it++) {
        int cur = it & 1;
        if (it + 1 < 8) {
            int nb = 1 - cur;
            int k0 = kBase + (it + 1) * 32;
            #pragma unroll
            for (int i = 0; i < 2; i++) {
                int row = frow + 32*i;
                cp16(sbase + (ABUF(nb) + row*LDK + fcg)*4, &A[(rBase+row)*DD + k0 + fcg]);
            }
            #pragma unroll
            for (int i = 0; i < 4; i++) {
                int row = frow + 32*i;
                cp16(sbase + (BBUF(nb) + row*LDK + fcg)*4, &W[(oBase+row)*DD + k0 + fcg]);
            }
            CP_COMMIT();
        }
        const float* as = &sm[ABUF(cur) + aBase];
        const float* bs = &sm[BBUF(cur) + bBase];
        #pragma unroll
        for (int ks = 0; ks < 4; ks++) {
            uint32_t af[2][4], bf[4][2];
            #pragma unroll
            for (int mt = 0; mt < 2; mt++) {
                #pragma unroll
                for (int j = 0; j < 4; j++)
                    af[mt][j] = __float_as_uint(as[(mt*16 + 8*(j&1))*LDK + ks*8 + 4*(j>>1)]);
            }
            #pragma unroll
            for (int nt = 0; nt < 4; nt++) {
                #pragma unroll
                for (int j = 0; j < 2; j++)
                    bf[nt][j] = __float_as_uint(bs[(nt*8)*LDK + ks*8 + 4*j]);
            }
            #pragma unroll
            for (int mt = 0; mt < 2; mt++)
                #pragma unroll
                for (int nt = 0; nt < 4; nt++)
                    mma_tf32(acc[mt][nt], af[mt], bf[nt]);
        }
        if (it + 1 < 8) CP_WAIT0();
        __syncthreads();
    }

    // write partial tile (no bias, no stats)
    #pragma unroll
    for (int nt = 0; nt < 4; nt++) {
        int col = oBase + wn*32 + nt*8 + (lane & 3)*2;
        #pragma unroll
        for (int mt = 0; mt < 2; mt++) {
            int row0 = rBase + wm*32 + mt*16 + (lane >> 2);
            *(float2*)&Z[row0*DD + col]     = make_float2(acc[mt][nt][0], acc[mt][nt][1]);
            *(float2*)&Z[(row0+8)*DD + col] = make_float2(acc[mt][nt][2], acc[mt][nt][3]);
        }
    }
}

// ---------------- combine partials + bias, fused BN partial stats ----------
// grid (64, 4), 256 threads: block = 64 rows x 128 cols
__global__ void __launch_bounds__(256) k_combine(const float* __restrict__ bias) {
    __shared__ float red[512];
    int rb = blockIdx.x;
    int ob = blockIdx.y;
    int t = threadIdx.x;
    int g = t >> 7, c = t & 127;
    int col = ob*128 + c;
    float bv = bias[col];
    float s = 0.0f, q = 0.0f;
    #pragma unroll 4
    for (int i = 0; i < 32; i++) {
        int row = rb*64 + g*32 + i;
        float v = g_z[row*DD + col] + g_z2[row*DD + col] + bv;
        g_z[row*DD + col] = v;
        s += v; q += v*v;
    }
    red[t] = s; red[256 + t] = q;
    __syncthreads();
    if (t < 128) {
        g_psum[rb*DD + ob*128 + t] = red[t]       + red[128 + t];
        g_psq [rb*DD + ob*128 + t] = red[256 + t] + red[384 + t];
    }
}

// ---------------- BN finalize (4 blocks x 128) ----------------
__global__ void k_finalize(const float* __restrict__ gma, const float* __restrict__ bta) {
    int o = blockIdx.x * 128 + threadIdx.x;
    float s = 0.0f, q = 0.0f;
    #pragma unroll 8
    for (int i = 0; i < 64; i++) { s += g_psum[i*DD + o]; q += g_psq[i*DD + o]; }
    float mean = s * (1.0f/4096.0f);
    float var  = q * (1.0f/4096.0f) - mean*mean;
    float inv  = rsqrtf(var + 1e-5f);
    float sc   = gma[o] * inv;
    g_scale[o] = sc;
    g_shift[o] = bta[o] - mean * sc;
}

// ---------------- BN apply + ReLU -> out[:, :, 15, :] ----------------
__global__ void k_apply(float* __restrict__ outp) {
    int i  = blockIdx.x * blockDim.x + threadIdx.x;
    int r  = i >> 7;
    int cw = i & 127;
    float4 z  = ((const float4*)g_z)[i];
    float4 sc = ((const float4*)g_scale)[cw];
    float4 sh = ((const float4*)g_shift)[cw];
    float4 h;
    h.x = fmaxf(fmaf(z.x, sc.x, sh.x), 0.0f);
    h.y = fmaxf(fmaf(z.y, sc.y, sh.y), 0.0f);
    h.z = fmaxf(fmaf(z.z, sc.z, sh.z), 0.0f);
    h.w = fmaxf(fmaf(z.w, sc.w, sh.w), 0.0f);
    *(float4*)&outp[r*(TT*DD) + 15*DD + cw*4] = h;
}

// ---------------- side stream + events (created pre-main, no allocs in launch) --
namespace {
struct SideStream {
    cudaStream_t s;
    cudaEvent_t evFork, evJoin;
    SideStream() {
        cudaStreamCreateWithFlags(&s, cudaStreamNonBlocking);
        cudaEventCreateWithFlags(&evFork, cudaEventDisableTiming);
        cudaEventCreateWithFlags(&evJoin, cudaEventDisableTiming);
        k_warm<<<1, 32, 0, s>>>();
        cudaStreamSynchronize(s);
    }
};
SideStream g_ss;
}

// ---------------- launcher ----------------
extern "C" void kernel_launch(void* const* d_in, const int* in_sizes, int n_in,
                              void* d_out, int out_size) {
    const float* pf  = (const float*)d_in[0];
    const float* bbx = (const float*)d_in[1];
    const float* w1  = (const float*)d_in[2];
    const float* b1  = (const float*)d_in[3];
    const float* g1  = (const float*)d_in[4];
    const float* be1 = (const float*)d_in[5];
    const float* w2  = (const float*)d_in[6];
    const float* b2  = (const float*)d_in[7];
    const float* g2  = (const float*)d_in[8];
    const float* be2 = (const float*)d_in[9];
    float* out = (float*)d_out;

    static int s_attr_done = 0;
    if (!s_attr_done) {
        cudaFuncSetAttribute(k_gemm_mma, cudaFuncAttributeMaxDynamicSharedMemorySize, GEMM_SMEM);
        s_attr_done = 1;
    }

    // fork: bulk copy of t=0..14 slices runs concurrently on the side stream
    cudaEventRecord(g_ss.evFork, 0);
    cudaStreamWaitEvent(g_ss.s, g_ss.evFork, 0);
    k_copy15<<<296, 256, 0, g_ss.s>>>((const float4*)pf, (float4*)out);
    cudaEventRecord(g_ss.evJoin, g_ss.s);

    // layer 1
    k_agg<<<dim3(64, 8), 128>>>(pf, bbx, 0);
    k_gemm_mma<<<dim3(64, 4, 2), 256, GEMM_SMEM>>>(w1);
    k_combine<<<dim3(64, 4), 256>>>(b1);
    k_finalize<<<4, 128>>>(g1, be1);

    // layer 2 (BN-apply of layer 1 fused into the aggregation load)
    k_agg<<<dim3(64, 8), 128>>>(nullptr, bbx, 1);
    k_gemm_mma<<<dim3(64, 4, 2), 256, GEMM_SMEM>>>(w2);
    k_combine<<<dim3(64, 4), 256>>>(b2);
    k_finalize<<<4, 128>>>(g2, be2);
    k_apply<<<2048, 256>>>(out);

    // join side stream before the graph/launch completes
    cudaStreamWaitEvent(0, g_ss.evJoin, 0);
}

// round 15
// speedup vs baseline: 1.1887x; 1.1887x over previous
#include <cuda_runtime.h>
#include <cstdint>

#define BB 64
#define NN 64
#define TT 16
#define DD 512
#define RR (BB*NN)          // 4096 rows (b,m)
#define THR2 (150.0f*150.0f)

// ---------------- scratch (device globals, no allocation) ----------------
// g_agg: FRAGMENT-ORDER layout:
//   off(r64, kg, rg, lane, j) = (r64*64 + kg)*512 + rg*128 + lane*4 + j
//   value = agg[r64*64 + rg*16 + lane/4 + 8*(j&1)][kg*8 + lane%4 + 4*(j>>1)]
__device__ float g_agg[RR*DD];
__device__ float g_z[RR*DD];        // pre-BN GEMM output [r][o] (row-major)
__device__ float g_wp1[DD*DD];      // W1 packed (fragment order)
__device__ float g_wp2[DD*DD];      // W2 packed
// packed W: off(o64, kg, cg, lane, j) = (o64*64 + kg)*512 + cg*64 + lane*2 + j
//   value = W[o64*64 + cg*8 + lane/4][kg*8 + lane%4 + 4*j]
__device__ float g_psum[64*DD];     // BN partial sums   [rTile][col]
__device__ float g_psq[64*DD];      // BN partial sumsq  [rTile][col]
__device__ float g_scale[DD];
__device__ float g_shift[DD];

// ---------------- warmup (forces stream resource materialization pre-main) --
__global__ void k_warm() {}

// ---------------- side-stream copy: out[:, :, t!=15, :] = pf ----------------
__global__ void __launch_bounds__(256) k_copy15(const float4* __restrict__ src,
                                                float4* __restrict__ dst) {
    int t  = threadIdx.x;
    int tt = blockIdx.y;          // 0..14
    int rb = blockIdx.x;          // 0..63
    #pragma unroll 4
    for (int j = t; j < 64*128; j += 256) {
        int k = j >> 7, w = j & 127;
        size_t idx = ((size_t)(rb*64 + k)*16 + tt) * 128 + w;
        dst[idx] = src[idx];
    }
}

// ---------------- pack W into fragment order (runs on side stream) ----------
// grid 512 = (o64 0..7)*(kg 0..63), block 128
__global__ void __launch_bounds__(128) k_packW(const float* __restrict__ W,
                                               float* __restrict__ outw) {
    __shared__ float smw[64*8];
    int blk = blockIdx.x;
    int o64 = blk >> 6, kg = blk & 63;
    int t = threadIdx.x;
    int r = t >> 1, kk = (t & 1) * 4;
    float4 v = *(const float4*)&W[(o64*64 + r)*DD + kg*8 + kk];
    *(float4*)&smw[r*8 + kk] = v;
    __syncthreads();
    int base = t * 4;
    float o[4];
    #pragma unroll
    for (int u = 0; u < 4; u++) {
        int idx = base + u;
        int cg = idx >> 6, rem = idx & 63;
        int lane2 = rem >> 1, j = idx & 1;
        o[u] = smw[(cg*8 + (lane2 >> 2))*8 + (lane2 & 3) + 4*j];
    }
    *(float4*)&outw[(o64*64 + kg)*512 + base] = make_float4(o[0], o[1], o[2], o[3]);
}

// ---------------- common MMA helper ----------------
__device__ __forceinline__ void mma_tf32(float* c, const uint32_t* a, const uint32_t* b) {
    asm volatile(
        "mma.sync.aligned.m16n8k8.row.col.f32.tf32.tf32.f32 "
        "{%0,%1,%2,%3}, {%4,%5,%6,%7}, {%8,%9}, {%0,%1,%2,%3};"
        : "+f"(c[0]), "+f"(c[1]), "+f"(c[2]), "+f"(c[3])
        : "r"(a[0]), "r"(a[1]), "r"(a[2]), "r"(a[3]), "r"(b[0]), "r"(b[1]));
}
__device__ __forceinline__ void cp16(uint32_t dst, const void* src) {
    asm volatile("cp.async.ca.shared.global [%0], [%1], 16;" :: "r"(dst), "l"(src));
}
#define CP_COMMIT() asm volatile("cp.async.commit_group;" ::: "memory")
#define CP_WAIT0()  asm volatile("cp.async.wait_group 0;" ::: "memory")

// ---------------- graph aggregation via tf32 MMA (adjacency fused) ----------------
// Output written to g_agg in FRAGMENT ORDER (staged through smem).
#define AGG_LD 68
__global__ void __launch_bounds__(128) k_agg(const float* __restrict__ pf,
                                             const float* __restrict__ bbx, int mode) {
    __shared__ float Asm[NN*AGG_LD];    // [m][n] stride 68
    __shared__ float Xs[NN*AGG_LD];     // [n][c] stride 68 (reused to stage D)
    __shared__ float cx[NN], cy[NN], invdeg[NN];
    int b = blockIdx.x;
    int cBase = blockIdx.y * 64;
    int t = threadIdx.x;
    int lane = t & 31, wid = t >> 5;
    int wm = wid >> 1, wn = wid & 1;     // 2x2 warps: 32 rows x 32 cols each

    if (t < NN) {
        const float* p = bbx + (b*NN + t)*4;
        cx[t] = p[0] + 0.5f*p[2];
        cy[t] = p[1] + 0.5f*p[3];
    }
    __syncthreads();
    if (t < NN) {
        float x0 = cx[t], y0 = cy[t];
        int cnt = 0;
        #pragma unroll 8
        for (int m = 0; m < NN; m++) {
            float dx = x0 - cx[m], dy = y0 - cy[m];
            if (m != t && dx*dx + dy*dy < THR2) cnt++;
        }
        invdeg[t] = 1.0f / ((float)(cnt + 1) + 1e-6f);
    }
    __syncthreads();
    #pragma unroll
    for (int i = 0; i < 32; i++) {
        int e = t + 128*i;
        int m = e >> 6, n = e & 63;
        float dx = cx[n]-cx[m], dy = cy[n]-cy[m];
        float d2 = dx*dx + dy*dy;
        Asm[m*AGG_LD + n] = (n == m || d2 < THR2) ? invdeg[n] : 0.0f;
    }
    #pragma unroll
    for (int i = 0; i < 8; i++) {
        int e  = t + 128*i;          // 0..1023
        int n  = e >> 4;
        int cg = (e & 15) * 4;
        float4 v;
        if (mode == 0) {
            v = *(const float4*)&pf[((b*NN + n)*TT + 15)*DD + cBase + cg];
        } else {
            float4 z  = *(const float4*)&g_z[(b*NN + n)*DD + cBase + cg];
            float4 sc = *(const float4*)&g_scale[cBase + cg];
            float4 sh = *(const float4*)&g_shift[cBase + cg];
            v.x = fmaxf(fmaf(z.x, sc.x, sh.x), 0.0f);
            v.y = fmaxf(fmaf(z.y, sc.y, sh.y), 0.0f);
            v.z = fmaxf(fmaf(z.z, sc.z, sh.z), 0.0f);
            v.w = fmaxf(fmaf(z.w, sc.w, sh.w), 0.0f);
        }
        *(float4*)&Xs[n*AGG_LD + cg] = v;
    }
    __syncthreads();

    float acc[2][4][4];
    #pragma unroll
    for (int mt = 0; mt < 2; mt++)
        #pragma unroll
        for (int nt = 0; nt < 4; nt++)
            #pragma unroll
            for (int j = 0; j < 4; j++) acc[mt][nt][j] = 0.0f;

    int ar = wm*32 + (lane >> 2);
    int bc = wn*32 + (lane >> 2);
    #pragma unroll
    for (int ks = 0; ks < 8; ks++) {
        uint32_t af[2][4], bf[4][2];
        #pragma unroll
        for (int mt = 0; mt < 2; mt++)
            #pragma unroll
            for (int j = 0; j < 4; j++)
                af[mt][j] = __float_as_uint(
                    Asm[(ar + mt*16 + 8*(j&1))*AGG_LD + ks*8 + (lane&3) + 4*(j>>1)]);
        #pragma unroll
        for (int nt = 0; nt < 4; nt++)
            #pragma unroll
            for (int j = 0; j < 2; j++)
                bf[nt][j] = __float_as_uint(
                    Xs[(ks*8 + (lane&3) + 4*j)*AGG_LD + bc + nt*8]);
        #pragma unroll
        for (int mt = 0; mt < 2; mt++)
            #pragma unroll
            for (int nt = 0; nt < 4; nt++)
                mma_tf32(acc[mt][nt], af[mt], bf[nt]);
    }

    // ---- stage D into Xs (local [m][c]) then write fragment-ordered g_agg ----
    __syncthreads();   // done reading Asm/Xs
    #pragma unroll
    for (int nt = 0; nt < 4; nt++) {
        int col = wn*32 + nt*8 + (lane & 3)*2;
        #pragma unroll
        for (int mt = 0; mt < 2; mt++) {
            int row0 = wm*32 + mt*16 + (lane >> 2);
            *(float2*)&Xs[row0*AGG_LD + col]     = make_float2(acc[mt][nt][0], acc[mt][nt][1]);
            *(float2*)&Xs[(row0+8)*AGG_LD + col] = make_float2(acc[mt][nt][2], acc[mt][nt][3]);
        }
    }
    __syncthreads();
    // packed block for (r64=b, kg = blockIdx.y*8 + kgl): 1024 float4, 8/thread
    float* outp = &g_agg[((size_t)b*64 + blockIdx.y*8)*512];
    #pragma unroll
    for (int i = 0; i < 8; i++) {
        int o = t*8 + i;             // float4 index 0..1023
        int kgl = o >> 7, rem = o & 127;
        int rg = rem >> 5, lane2 = rem & 31;
        int rbase = rg*16 + (lane2 >> 2);
        int kbase = kgl*8 + (lane2 & 3);
        float v0 = Xs[rbase*AGG_LD + kbase];
        float v1 = Xs[(rbase+8)*AGG_LD + kbase];
        float v2 = Xs[rbase*AGG_LD + kbase + 4];
        float v3 = Xs[(rbase+8)*AGG_LD + kbase + 4];
        *(float4*)&outp[o*4] = make_float4(v0, v1, v2, v3);
    }
}

// ---------------- tf32 mma.sync GEMM + fused BN partial stats ----------------
// Operands pre-packed in fragment order -> fills are linear memcpys,
// fragment loads are LDS.128 (A) / LDS.64 (B), conflict-free.
// Block 64x128, BK=32, 8 warps (2M x 4N), warp tile 32x32.
#define STGF 6144                  // floats per stage: A 2048 + B 4096
#define ABUF(s) ((s)*STGF)
#define BBUF(s) ((s)*STGF + 2048)
#define GEMM_SMEM (2*STGF*4)       // 48KB

__global__ void __launch_bounds__(256, 3) k_gemm_mma(const float* __restrict__ Wp,
                                                     const float* __restrict__ bias) {
    extern __shared__ float sm[];
    uint32_t sbase = (uint32_t)__cvta_generic_to_shared(sm);
    int t = threadIdx.x;
    int lane = t & 31;
    int wid = t >> 5;
    int wm = wid >> 2, wn = wid & 3;
    int rBase = blockIdx.x * 64;
    int oBase = blockIdx.y * 128;
    const float* A = g_agg;

    float acc[2][4][4];
    #pragma unroll
    for (int mt = 0; mt < 2; mt++)
        #pragma unroll
        for (int nt = 0; nt < 4; nt++)
            #pragma unroll
            for (int j = 0; j < 4; j++) acc[mt][nt][j] = 0.0f;

    // fill chunk 0 into stage 0 (linear copies)
    {
        size_t abase = ((size_t)blockIdx.x*64 + 0)*512;
        #pragma unroll
        for (int i = 0; i < 2; i++) {
            int idx = t + 256*i;
            cp16(sbase + (ABUF(0) + idx*4)*4, &A[abase + idx*4]);
        }
        #pragma unroll
        for (int h = 0; h < 2; h++) {
            size_t bbase = (((size_t)(blockIdx.y*2 + h))*64 + 0)*512;
            #pragma unroll
            for (int i = 0; i < 2; i++) {
                int idx = t + 256*i;
                cp16(sbase + (BBUF(0) + h*2048 + idx*4)*4, &Wp[bbase + idx*4]);
            }
        }
        CP_COMMIT();
        CP_WAIT0();
        __syncthreads();
    }

    #pragma unroll 1
    for (int it = 0; it < 16; it++) {
        int cur = it & 1;
        if (it + 1 < 16) {
            int nb = 1 - cur;
            size_t abase = ((size_t)blockIdx.x*64 + 4*(it+1))*512;
            #pragma unroll
            for (int i = 0; i < 2; i++) {
                int idx = t + 256*i;
                cp16(sbase + (ABUF(nb) + idx*4)*4, &A[abase + idx*4]);
            }
            #pragma unroll
            for (int h = 0; h < 2; h++) {
                size_t bbase = (((size_t)(blockIdx.y*2 + h))*64 + 4*(it+1))*512;
                #pragma unroll
                for (int i = 0; i < 2; i++) {
                    int idx = t + 256*i;
                    cp16(sbase + (BBUF(nb) + h*2048 + idx*4)*4, &Wp[bbase + idx*4]);
                }
            }
            CP_COMMIT();
        }
        const float* as = &sm[ABUF(cur)];
        const float* bs = &sm[BBUF(cur) + (wn >> 1)*2048];
        #pragma unroll
        for (int ks = 0; ks < 4; ks++) {
            uint32_t af[2][4], bf[4][2];
            #pragma unroll
            for (int mt = 0; mt < 2; mt++) {
                float4 v = *(const float4*)&as[ks*512 + (wm*2 + mt)*128 + lane*4];
                af[mt][0] = __float_as_uint(v.x); af[mt][1] = __float_as_uint(v.y);
                af[mt][2] = __float_as_uint(v.z); af[mt][3] = __float_as_uint(v.w);
            }
            #pragma unroll
            for (int nt = 0; nt < 4; nt++) {
                float2 v = *(const float2*)&bs[ks*512 + ((wn&1)*4 + nt)*64 + lane*2];
                bf[nt][0] = __float_as_uint(v.x); bf[nt][1] = __float_as_uint(v.y);
            }
            #pragma unroll
            for (int mt = 0; mt < 2; mt++)
                #pragma unroll
                for (int nt = 0; nt < 4; nt++)
                    mma_tf32(acc[mt][nt], af[mt], bf[nt]);
        }
        if (it + 1 < 16) CP_WAIT0();
        __syncthreads();
    }

    // ---- epilogue: bias add, write g_z (row-major), per-column stats ----
    float s[4][2], q[4][2];
    #pragma unroll
    for (int nt = 0; nt < 4; nt++) { s[nt][0]=s[nt][1]=q[nt][0]=q[nt][1]=0.0f; }

    #pragma unroll
    for (int nt = 0; nt < 4; nt++) {
        int col = oBase + wn*32 + nt*8 + (lane & 3)*2;
        float2 bv = *(const float2*)&bias[col];
        #pragma unroll
        for (int mt = 0; mt < 2; mt++) {
            int row0 = rBase + wm*32 + mt*16 + (lane >> 2);
            float2 v0 = make_float2(acc[mt][nt][0] + bv.x, acc[mt][nt][1] + bv.y);
            float2 v1 = make_float2(acc[mt][nt][2] + bv.x, acc[mt][nt][3] + bv.y);
            *(float2*)&g_z[row0*DD + col]     = v0;
            *(float2*)&g_z[(row0+8)*DD + col] = v1;
            s[nt][0] += v0.x + v1.x;  s[nt][1] += v0.y + v1.y;
            q[nt][0] += v0.x*v0.x + v1.x*v1.x;
            q[nt][1] += v0.y*v0.y + v1.y*v1.y;
        }
    }
    #pragma unroll
    for (int off = 4; off < 32; off <<= 1) {
        #pragma unroll
        for (int nt = 0; nt < 4; nt++) {
            s[nt][0] += __shfl_xor_sync(0xffffffffu, s[nt][0], off);
            s[nt][1] += __shfl_xor_sync(0xffffffffu, s[nt][1], off);
            q[nt][0] += __shfl_xor_sync(0xffffffffu, q[nt][0], off);
            q[nt][1] += __shfl_xor_sync(0xffffffffu, q[nt][1], off);
        }
    }
    float* red = sm;
    __syncthreads();
    if (lane < 4) {
        #pragma unroll
        for (int nt = 0; nt < 4; nt++) {
            int coll = wn*32 + nt*8 + lane*2;
            red[wm*256 +       coll    ] = s[nt][0];
            red[wm*256 +       coll + 1] = s[nt][1];
            red[wm*256 + 128 + coll    ] = q[nt][0];
            red[wm*256 + 128 + coll + 1] = q[nt][1];
        }
    }
    __syncthreads();
    if (t < 128) {
        float st = red[t]       + red[256 + t];
        float qt = red[128 + t] + red[384 + t];
        g_psum[blockIdx.x*DD + oBase + t] = st;
        g_psq [blockIdx.x*DD + oBase + t] = qt;
    }
}

// ---------------- BN finalize (4 blocks x 128) ----------------
__global__ void k_finalize(const float* __restrict__ gma, const float* __restrict__ bta) {
    int o = blockIdx.x * 128 + threadIdx.x;
    float s = 0.0f, q = 0.0f;
    #pragma unroll 8
    for (int i = 0; i < 64; i++) { s += g_psum[i*DD + o]; q += g_psq[i*DD + o]; }
    float mean = s * (1.0f/4096.0f);
    float var  = q * (1.0f/4096.0f) - mean*mean;
    float inv  = rsqrtf(var + 1e-5f);
    float sc   = gma[o] * inv;
    g_scale[o] = sc;
    g_shift[o] = bta[o] - mean * sc;
}

// ---------------- BN apply + ReLU -> out[:, :, 15, :] ----------------
__global__ void k_apply(float* __restrict__ outp) {
    int i  = blockIdx.x * blockDim.x + threadIdx.x;
    int r  = i >> 7;
    int cw = i & 127;
    float4 z  = ((const float4*)g_z)[i];
    float4 sc = ((const float4*)g_scale)[cw];
    float4 sh = ((const float4*)g_shift)[cw];
    float4 h;
    h.x = fmaxf(fmaf(z.x, sc.x, sh.x), 0.0f);
    h.y = fmaxf(fmaf(z.y, sc.y, sh.y), 0.0f);
    h.z = fmaxf(fmaf(z.z, sc.z, sh.z), 0.0f);
    h.w = fmaxf(fmaf(z.w, sc.w, sh.w), 0.0f);
    *(float4*)&outp[r*(TT*DD) + 15*DD + cw*4] = h;
}

// ---------------- side stream + events (created pre-main, no allocs in launch) --
namespace {
struct SideStream {
    cudaStream_t s;
    cudaEvent_t evFork, evJoin, evPack;
    SideStream() {
        cudaStreamCreateWithFlags(&s, cudaStreamNonBlocking);
        cudaEventCreateWithFlags(&evFork, cudaEventDisableTiming);
        cudaEventCreateWithFlags(&evJoin, cudaEventDisableTiming);
        cudaEventCreateWithFlags(&evPack, cudaEventDisableTiming);
        k_warm<<<1, 32, 0, s>>>();
        cudaStreamSynchronize(s);
    }
};
SideStream g_ss;
}

// ---------------- launcher ----------------
extern "C" void kernel_launch(void* const* d_in, const int* in_sizes, int n_in,
                              void* d_out, int out_size) {
    const float* pf  = (const float*)d_in[0];
    const float* bbx = (const float*)d_in[1];
    const float* w1  = (const float*)d_in[2];
    const float* b1  = (const float*)d_in[3];
    const float* g1  = (const float*)d_in[4];
    const float* be1 = (const float*)d_in[5];
    const float* w2  = (const float*)d_in[6];
    const float* b2  = (const float*)d_in[7];
    const float* g2  = (const float*)d_in[8];
    const float* be2 = (const float*)d_in[9];
    float* out = (float*)d_out;

    static int s_attr_done = 0;
    if (!s_attr_done) {
        cudaFuncSetAttribute(k_gemm_mma, cudaFuncAttributeMaxDynamicSharedMemorySize, GEMM_SMEM);
        s_attr_done = 1;
    }

    float* wp1; cudaGetSymbolAddress((void**)&wp1, g_wp1);
    float* wp2; cudaGetSymbolAddress((void**)&wp2, g_wp2);

    // fork: pack W1/W2 then bulk-copy t=0..14 slices, all on the side stream
    cudaEventRecord(g_ss.evFork, 0);
    cudaStreamWaitEvent(g_ss.s, g_ss.evFork, 0);
    k_packW<<<512, 128, 0, g_ss.s>>>(w1, wp1);
    k_packW<<<512, 128, 0, g_ss.s>>>(w2, wp2);
    cudaEventRecord(g_ss.evPack, g_ss.s);
    k_copy15<<<dim3(64, 15), 256, 0, g_ss.s>>>((const float4*)pf, (float4*)out);
    cudaEventRecord(g_ss.evJoin, g_ss.s);

    // layer 1
    k_agg<<<dim3(64, 8), 128>>>(pf, bbx, 0);
    cudaStreamWaitEvent(0, g_ss.evPack, 0);     // W packs must be done
    k_gemm_mma<<<dim3(64, 4), 256, GEMM_SMEM>>>(wp1, b1);
    k_finalize<<<4, 128>>>(g1, be1);

    // layer 2 (BN-apply of layer 1 fused into the aggregation load)
    k_agg<<<dim3(64, 8), 128>>>(nullptr, bbx, 1);
    k_gemm_mma<<<dim3(64, 4), 256, GEMM_SMEM>>>(wp2, b2);
    k_finalize<<<4, 128>>>(g2, be2);
    k_apply<<<2048, 256>>>(out);

    // join side stream before the graph/launch completes
    cudaStreamWaitEvent(0, g_ss.evJoin, 0);
}

// round 16
// speedup vs baseline: 1.2426x; 1.0453x over previous
#include <cuda_runtime.h>
#include <cstdint>

#define BB 64
#define NN 64
#define TT 16
#define DD 512
#define RR (BB*NN)          // 4096 rows (b,m)
#define THR2 (150.0f*150.0f)

// ---------------- scratch (device globals, no allocation) ----------------
// g_agg: FRAGMENT-ORDER layout:
//   off(r64, kg, rg, lane, j) = (r64*64 + kg)*512 + rg*128 + lane*4 + j
__device__ float g_agg[RR*DD];
__device__ float g_z[RR*DD];        // pre-BN GEMM output [r][o] (row-major)
__device__ float g_wp1[DD*DD];      // W1 packed (fragment order)
__device__ float g_wp2[DD*DD];      // W2 packed
__device__ float g_psum[64*DD];     // BN partial sums   [rTile][col]
__device__ float g_psq[64*DD];      // BN partial sumsq  [rTile][col]
__device__ float g_scale[DD];
__device__ float g_shift[DD];

// ---------------- warmup (forces stream resource materialization pre-main) --
__global__ void k_warm() {}

// ---------------- side-stream copy: out[:, :, t!=15, :] = pf ----------------
// LOW-FOOTPRINT: 74 blocks only, 16-deep unroll for MLP; near-peak DRAM BW
// while leaving ~87% of CTA slots to the compute chain.
#define CPY_BLOCKS 74
__global__ void __launch_bounds__(256) k_copy15(const float4* __restrict__ src,
                                                float4* __restrict__ dst) {
    // 1920 chunks of 4096 float4 cover RR*15*128 = 7,864,320 float4
    for (int chunk = blockIdx.x; chunk < 1920; chunk += CPY_BLOCKS) {
        int base = chunk * 4096 + threadIdx.x;
        #pragma unroll
        for (int u = 0; u < 16; u++) {
            int e = base + u * 256;
            int r = e / 1920;
            int rem = e - r * 1920;
            size_t idx = (size_t)r * 2048 + rem;
            dst[idx] = src[idx];
        }
    }
}

// ---------------- pack W into fragment order (runs on side stream) ----------
__global__ void __launch_bounds__(128) k_packW(const float* __restrict__ W,
                                               float* __restrict__ outw) {
    __shared__ float smw[64*8];
    int blk = blockIdx.x;
    int o64 = blk >> 6, kg = blk & 63;
    int t = threadIdx.x;
    int r = t >> 1, kk = (t & 1) * 4;
    float4 v = *(const float4*)&W[(o64*64 + r)*DD + kg*8 + kk];
    *(float4*)&smw[r*8 + kk] = v;
    __syncthreads();
    int base = t * 4;
    float o[4];
    #pragma unroll
    for (int u = 0; u < 4; u++) {
        int idx = base + u;
        int cg = idx >> 6, rem = idx & 63;
        int lane2 = rem >> 1, j = idx & 1;
        o[u] = smw[(cg*8 + (lane2 >> 2))*8 + (lane2 & 3) + 4*j];
    }
    *(float4*)&outw[(o64*64 + kg)*512 + base] = make_float4(o[0], o[1], o[2], o[3]);
}

// ---------------- common MMA helper ----------------
__device__ __forceinline__ void mma_tf32(float* c, const uint32_t* a, const uint32_t* b) {
    asm volatile(
        "mma.sync.aligned.m16n8k8.row.col.f32.tf32.tf32.f32 "
        "{%0,%1,%2,%3}, {%4,%5,%6,%7}, {%8,%9}, {%0,%1,%2,%3};"
        : "+f"(c[0]), "+f"(c[1]), "+f"(c[2]), "+f"(c[3])
        : "r"(a[0]), "r"(a[1]), "r"(a[2]), "r"(a[3]), "r"(b[0]), "r"(b[1]));
}
__device__ __forceinline__ void cp16(uint32_t dst, const void* src) {
    asm volatile("cp.async.ca.shared.global [%0], [%1], 16;" :: "r"(dst), "l"(src));
}
#define CP_COMMIT() asm volatile("cp.async.commit_group;" ::: "memory")
#define CP_WAIT0()  asm volatile("cp.async.wait_group 0;" ::: "memory")

// ---------------- graph aggregation via tf32 MMA (adjacency fused) ----------------
// Output written to g_agg in FRAGMENT ORDER (staged through smem).
#define AGG_LD 68
__global__ void __launch_bounds__(128) k_agg(const float* __restrict__ pf,
                                             const float* __restrict__ bbx, int mode) {
    __shared__ float Asm[NN*AGG_LD];    // [m][n] stride 68
    __shared__ float Xs[NN*AGG_LD];     // [n][c] stride 68 (reused to stage D)
    __shared__ float cx[NN], cy[NN], invdeg[NN];
    int b = blockIdx.x;
    int cBase = blockIdx.y * 64;
    int t = threadIdx.x;
    int lane = t & 31, wid = t >> 5;
    int wm = wid >> 1, wn = wid & 1;     // 2x2 warps: 32 rows x 32 cols each

    if (t < NN) {
        const float* p = bbx + (b*NN + t)*4;
        cx[t] = p[0] + 0.5f*p[2];
        cy[t] = p[1] + 0.5f*p[3];
    }
    __syncthreads();
    if (t < NN) {
        float x0 = cx[t], y0 = cy[t];
        int cnt = 0;
        #pragma unroll 8
        for (int m = 0; m < NN; m++) {
            float dx = x0 - cx[m], dy = y0 - cy[m];
            if (m != t && dx*dx + dy*dy < THR2) cnt++;
        }
        invdeg[t] = 1.0f / ((float)(cnt + 1) + 1e-6f);
    }
    __syncthreads();
    #pragma unroll
    for (int i = 0; i < 32; i++) {
        int e = t + 128*i;
        int m = e >> 6, n = e & 63;
        float dx = cx[n]-cx[m], dy = cy[n]-cy[m];
        float d2 = dx*dx + dy*dy;
        Asm[m*AGG_LD + n] = (n == m || d2 < THR2) ? invdeg[n] : 0.0f;
    }
    #pragma unroll
    for (int i = 0; i < 8; i++) {
        int e  = t + 128*i;          // 0..1023
        int n  = e >> 4;
        int cg = (e & 15) * 4;
        float4 v;
        if (mode == 0) {
            v = *(const float4*)&pf[((b*NN + n)*TT + 15)*DD + cBase + cg];
        } else {
            float4 z  = *(const float4*)&g_z[(b*NN + n)*DD + cBase + cg];
            float4 sc = *(const float4*)&g_scale[cBase + cg];
            float4 sh = *(const float4*)&g_shift[cBase + cg];
            v.x = fmaxf(fmaf(z.x, sc.x, sh.x), 0.0f);
            v.y = fmaxf(fmaf(z.y, sc.y, sh.y), 0.0f);
            v.z = fmaxf(fmaf(z.z, sc.z, sh.z), 0.0f);
            v.w = fmaxf(fmaf(z.w, sc.w, sh.w), 0.0f);
        }
        *(float4*)&Xs[n*AGG_LD + cg] = v;
    }
    __syncthreads();

    float acc[2][4][4];
    #pragma unroll
    for (int mt = 0; mt < 2; mt++)
        #pragma unroll
        for (int nt = 0; nt < 4; nt++)
            #pragma unroll
            for (int j = 0; j < 4; j++) acc[mt][nt][j] = 0.0f;

    int ar = wm*32 + (lane >> 2);
    int bc = wn*32 + (lane >> 2);
    #pragma unroll
    for (int ks = 0; ks < 8; ks++) {
        uint32_t af[2][4], bf[4][2];
        #pragma unroll
        for (int mt = 0; mt < 2; mt++)
            #pragma unroll
            for (int j = 0; j < 4; j++)
                af[mt][j] = __float_as_uint(
                    Asm[(ar + mt*16 + 8*(j&1))*AGG_LD + ks*8 + (lane&3) + 4*(j>>1)]);
        #pragma unroll
        for (int nt = 0; nt < 4; nt++)
            #pragma unroll
            for (int j = 0; j < 2; j++)
                bf[nt][j] = __float_as_uint(
                    Xs[(ks*8 + (lane&3) + 4*j)*AGG_LD + bc + nt*8]);
        #pragma unroll
        for (int mt = 0; mt < 2; mt++)
            #pragma unroll
            for (int nt = 0; nt < 4; nt++)
                mma_tf32(acc[mt][nt], af[mt], bf[nt]);
    }

    // ---- stage D into Xs (local [m][c]) then write fragment-ordered g_agg ----
    __syncthreads();   // done reading Asm/Xs
    #pragma unroll
    for (int nt = 0; nt < 4; nt++) {
        int col = wn*32 + nt*8 + (lane & 3)*2;
        #pragma unroll
        for (int mt = 0; mt < 2; mt++) {
            int row0 = wm*32 + mt*16 + (lane >> 2);
            *(float2*)&Xs[row0*AGG_LD + col]     = make_float2(acc[mt][nt][0], acc[mt][nt][1]);
            *(float2*)&Xs[(row0+8)*AGG_LD + col] = make_float2(acc[mt][nt][2], acc[mt][nt][3]);
        }
    }
    __syncthreads();
    float* outp = &g_agg[((size_t)b*64 + blockIdx.y*8)*512];
    #pragma unroll
    for (int i = 0; i < 8; i++) {
        int o = t*8 + i;             // float4 index 0..1023
        int kgl = o >> 7, rem = o & 127;
        int rg = rem >> 5, lane2 = rem & 31;
        int rbase = rg*16 + (lane2 >> 2);
        int kbase = kgl*8 + (lane2 & 3);
        float v0 = Xs[rbase*AGG_LD + kbase];
        float v1 = Xs[(rbase+8)*AGG_LD + kbase];
        float v2 = Xs[rbase*AGG_LD + kbase + 4];
        float v3 = Xs[(rbase+8)*AGG_LD + kbase + 4];
        *(float4*)&outp[o*4] = make_float4(v0, v1, v2, v3);
    }
}

// ---------------- tf32 mma.sync GEMM + fused BN partial stats ----------------
// Operands pre-packed in fragment order; fills are linear cp.async memcpys,
// fragment loads are LDS.128 (A) / LDS.64 (B), conflict-free.
#define STGF 6144                  // floats per stage: A 2048 + B 4096
#define ABUF(s) ((s)*STGF)
#define BBUF(s) ((s)*STGF + 2048)
#define GEMM_SMEM (2*STGF*4)       // 48KB

__global__ void __launch_bounds__(256, 3) k_gemm_mma(const float* __restrict__ Wp,
                                                     const float* __restrict__ bias) {
    extern __shared__ float sm[];
    uint32_t sbase = (uint32_t)__cvta_generic_to_shared(sm);
    int t = threadIdx.x;
    int lane = t & 31;
    int wid = t >> 5;
    int wm = wid >> 2, wn = wid & 3;
    int rBase = blockIdx.x * 64;
    int oBase = blockIdx.y * 128;
    const float* A = g_agg;

    float acc[2][4][4];
    #pragma unroll
    for (int mt = 0; mt < 2; mt++)
        #pragma unroll
        for (int nt = 0; nt < 4; nt++)
            #pragma unroll
            for (int j = 0; j < 4; j++) acc[mt][nt][j] = 0.0f;

    {
        size_t abase = ((size_t)blockIdx.x*64 + 0)*512;
        #pragma unroll
        for (int i = 0; i < 2; i++) {
            int idx = t + 256*i;
            cp16(sbase + (ABUF(0) + idx*4)*4, &A[abase + idx*4]);
        }
        #pragma unroll
        for (int h = 0; h < 2; h++) {
            size_t bbase = (((size_t)(blockIdx.y*2 + h))*64 + 0)*512;
            #pragma unroll
            for (int i = 0; i < 2; i++) {
                int idx = t + 256*i;
                cp16(sbase + (BBUF(0) + h*2048 + idx*4)*4, &Wp[bbase + idx*4]);
            }
        }
        CP_COMMIT();
        CP_WAIT0();
        __syncthreads();
    }

    #pragma unroll 1
    for (int it = 0; it < 16; it++) {
        int cur = it & 1;
        if (it + 1 < 16) {
            int nb = 1 - cur;
            size_t abase = ((size_t)blockIdx.x*64 + 4*(it+1))*512;
            #pragma unroll
            for (int i = 0; i < 2; i++) {
                int idx = t + 256*i;
                cp16(sbase + (ABUF(nb) + idx*4)*4, &A[abase + idx*4]);
            }
            #pragma unroll
            for (int h = 0; h < 2; h++) {
                size_t bbase = (((size_t)(blockIdx.y*2 + h))*64 + 4*(it+1))*512;
                #pragma unroll
                for (int i = 0; i < 2; i++) {
                    int idx = t + 256*i;
                    cp16(sbase + (BBUF(nb) + h*2048 + idx*4)*4, &Wp[bbase + idx*4]);
                }
            }
            CP_COMMIT();
        }
        const float* as = &sm[ABUF(cur)];
        const float* bs = &sm[BBUF(cur) + (wn >> 1)*2048];
        #pragma unroll
        for (int ks = 0; ks < 4; ks++) {
            uint32_t af[2][4], bf[4][2];
            #pragma unroll
            for (int mt = 0; mt < 2; mt++) {
                float4 v = *(const float4*)&as[ks*512 + (wm*2 + mt)*128 + lane*4];
                af[mt][0] = __float_as_uint(v.x); af[mt][1] = __float_as_uint(v.y);
                af[mt][2] = __float_as_uint(v.z); af[mt][3] = __float_as_uint(v.w);
            }
            #pragma unroll
            for (int nt = 0; nt < 4; nt++) {
                float2 v = *(const float2*)&bs[ks*512 + ((wn&1)*4 + nt)*64 + lane*2];
                bf[nt][0] = __float_as_uint(v.x); bf[nt][1] = __float_as_uint(v.y);
            }
            #pragma unroll
            for (int mt = 0; mt < 2; mt++)
                #pragma unroll
                for (int nt = 0; nt < 4; nt++)
                    mma_tf32(acc[mt][nt], af[mt], bf[nt]);
        }
        if (it + 1 < 16) CP_WAIT0();
        __syncthreads();
    }

    // ---- epilogue: bias add, write g_z (row-major), per-column stats ----
    float s[4][2], q[4][2];
    #pragma unroll
    for (int nt = 0; nt < 4; nt++) { s[nt][0]=s[nt][1]=q[nt][0]=q[nt][1]=0.0f; }

    #pragma unroll
    for (int nt = 0; nt < 4; nt++) {
        int col = oBase + wn*32 + nt*8 + (lane & 3)*2;
        float2 bv = *(const float2*)&bias[col];
        #pragma unroll
        for (int mt = 0; mt < 2; mt++) {
            int row0 = rBase + wm*32 + mt*16 + (lane >> 2);
            float2 v0 = make_float2(acc[mt][nt][0] + bv.x, acc[mt][nt][1] + bv.y);
            float2 v1 = make_float2(acc[mt][nt][2] + bv.x, acc[mt][nt][3] + bv.y);
            *(float2*)&g_z[row0*DD + col]     = v0;
            *(float2*)&g_z[(row0+8)*DD + col] = v1;
            s[nt][0] += v0.x + v1.x;  s[nt][1] += v0.y + v1.y;
            q[nt][0] += v0.x*v0.x + v1.x*v1.x;
            q[nt][1] += v0.y*v0.y + v1.y*v1.y;
        }
    }
    #pragma unroll
    for (int off = 4; off < 32; off <<= 1) {
        #pragma unroll
        for (int nt = 0; nt < 4; nt++) {
            s[nt][0] += __shfl_xor_sync(0xffffffffu, s[nt][0], off);
            s[nt][1] += __shfl_xor_sync(0xffffffffu, s[nt][1], off);
            q[nt][0] += __shfl_xor_sync(0xffffffffu, q[nt][0], off);
            q[nt][1] += __shfl_xor_sync(0xffffffffu, q[nt][1], off);
        }
    }
    float* red = sm;
    __syncthreads();
    if (lane < 4) {
        #pragma unroll
        for (int nt = 0; nt < 4; nt++) {
            int coll = wn*32 + nt*8 + lane*2;
            red[wm*256 +       coll    ] = s[nt][0];
            red[wm*256 +       coll + 1] = s[nt][1];
            red[wm*256 + 128 + coll    ] = q[nt][0];
            red[wm*256 + 128 + coll + 1] = q[nt][1];
        }
    }
    __syncthreads();
    if (t < 128) {
        float st = red[t]       + red[256 + t];
        float qt = red[128 + t] + red[384 + t];
        g_psum[blockIdx.x*DD + oBase + t] = st;
        g_psq [blockIdx.x*DD + oBase + t] = qt;
    }
}

// ---------------- BN finalize (4 blocks x 128) ----------------
__global__ void k_finalize(const float* __restrict__ gma, const float* __restrict__ bta) {
    int o = blockIdx.x * 128 + threadIdx.x;
    float s = 0.0f, q = 0.0f;
    #pragma unroll 8
    for (int i = 0; i < 64; i++) { s += g_psum[i*DD + o]; q += g_psq[i*DD + o]; }
    float mean = s * (1.0f/4096.0f);
    float var  = q * (1.0f/4096.0f) - mean*mean;
    float inv  = rsqrtf(var + 1e-5f);
    float sc   = gma[o] * inv;
    g_scale[o] = sc;
    g_shift[o] = bta[o] - mean * sc;
}

// ---------------- BN apply + ReLU -> out[:, :, 15, :] ----------------
__global__ void k_apply(float* __restrict__ outp) {
    int i  = blockIdx.x * blockDim.x + threadIdx.x;
    int r  = i >> 7;
    int cw = i & 127;
    float4 z  = ((const float4*)g_z)[i];
    float4 sc = ((const float4*)g_scale)[cw];
    float4 sh = ((const float4*)g_shift)[cw];
    float4 h;
    h.x = fmaxf(fmaf(z.x, sc.x, sh.x), 0.0f);
    h.y = fmaxf(fmaf(z.y, sc.y, sh.y), 0.0f);
    h.z = fmaxf(fmaf(z.z, sc.z, sh.z), 0.0f);
    h.w = fmaxf(fmaf(z.w, sc.w, sh.w), 0.0f);
    *(float4*)&outp[r*(TT*DD) + 15*DD + cw*4] = h;
}

// ---------------- side stream (lowest priority) + events ----------------
namespace {
struct SideStream {
    cudaStream_t s;
    cudaEvent_t evFork, evJoin, evPack;
    SideStream() {
        int loPri = 0, hiPri = 0;
        cudaDeviceGetStreamPriorityRange(&loPri, &hiPri);
        cudaStreamCreateWithPriority(&s, cudaStreamNonBlocking, loPri);
        cudaEventCreateWithFlags(&evFork, cudaEventDisableTiming);
        cudaEventCreateWithFlags(&evJoin, cudaEventDisableTiming);
        cudaEventCreateWithFlags(&evPack, cudaEventDisableTiming);
        k_warm<<<1, 32, 0, s>>>();
        cudaStreamSynchronize(s);
    }
};
SideStream g_ss;
}

// ---------------- launcher ----------------
extern "C" void kernel_launch(void* const* d_in, const int* in_sizes, int n_in,
                              void* d_out, int out_size) {
    const float* pf  = (const float*)d_in[0];
    const float* bbx = (const float*)d_in[1];
    const float* w1  = (const float*)d_in[2];
    const float* b1  = (const float*)d_in[3];
    const float* g1  = (const float*)d_in[4];
    const float* be1 = (const float*)d_in[5];
    const float* w2  = (const float*)d_in[6];
    const float* b2  = (const float*)d_in[7];
    const float* g2  = (const float*)d_in[8];
    const float* be2 = (const float*)d_in[9];
    float* out = (float*)d_out;

    static int s_attr_done = 0;
    if (!s_attr_done) {
        cudaFuncSetAttribute(k_gemm_mma, cudaFuncAttributeMaxDynamicSharedMemorySize, GEMM_SMEM);
        s_attr_done = 1;
    }

    float* wp1; cudaGetSymbolAddress((void**)&wp1, g_wp1);
    float* wp2; cudaGetSymbolAddress((void**)&wp2, g_wp2);

    // fork: pack W1/W2 then low-footprint bulk copy, all on low-priority side stream
    cudaEventRecord(g_ss.evFork, 0);
    cudaStreamWaitEvent(g_ss.s, g_ss.evFork, 0);
    k_packW<<<512, 128, 0, g_ss.s>>>(w1, wp1);
    k_packW<<<512, 128, 0, g_ss.s>>>(w2, wp2);
    cudaEventRecord(g_ss.evPack, g_ss.s);
    k_copy15<<<CPY_BLOCKS, 256, 0, g_ss.s>>>((const float4*)pf, (float4*)out);
    cudaEventRecord(g_ss.evJoin, g_ss.s);

    // layer 1
    k_agg<<<dim3(64, 8), 128>>>(pf, bbx, 0);
    cudaStreamWaitEvent(0, g_ss.evPack, 0);     // W packs must be done
    k_gemm_mma<<<dim3(64, 4), 256, GEMM_SMEM>>>(wp1, b1);
    k_finalize<<<4, 128>>>(g1, be1);

    // layer 2 (BN-apply of layer 1 fused into the aggregation load)
    k_agg<<<dim3(64, 8), 128>>>(nullptr, bbx, 1);
    k_gemm_mma<<<dim3(64, 4), 256, GEMM_SMEM>>>(wp2, b2);
    k_finalize<<<4, 128>>>(g2, be2);
    k_apply<<<2048, 256>>>(out);

    // join side stream before the graph/launch completes
    cudaStreamWaitEvent(0, g_ss.evJoin, 0);
}